// round 4
// baseline (speedup 1.0000x reference)
#include <cuda_runtime.h>
#include <cmath>

#define HID  640
#define ADIM 128
#define CPB  18      // chunks (blocks) per batch in pass1 -> 16*18 = 288 blocks
#define MAXB 16

// ---- device scratch (no allocations allowed) ----
__device__ float g_q[MAXB * ADIM];                 // q[b] = Wq @ pos[b]
__device__ float g_r[MAXB * HID];                  // r[b] = scale * Wk^T q[b]
__device__ float g_pacc[MAXB * CPB * HID];         // per-block partial weighted sums
__device__ float g_pm[MAXB * CPB];                 // per-block running max
__device__ float g_ps[MAXB * CPB];                 // per-block sum of exp
__device__ float g_y[MAXB * HID];                  // Wv @ pooled (pre-LN)

// ---------------------------------------------------------------------------
// Kernel 1a: q[b,a] = dot(Wq[a,:], pos[b,:])   — one warp per output
// ---------------------------------------------------------------------------
__global__ void __launch_bounds__(256) k_q(const float* __restrict__ pos,
                                           const float* __restrict__ Wq) {
    int gw   = blockIdx.x * 8 + (threadIdx.x >> 5);   // 0..2047
    int lane = threadIdx.x & 31;
    int b = gw >> 7;
    int a = gw & 127;

    const float* wr = Wq + (size_t)a * HID;
    const float* pr = pos + (size_t)b * HID;
    float s = 0.f;
    #pragma unroll
    for (int k = 0; k < HID / 32; k++) {
        int h = lane + 32 * k;
        s += wr[h] * pr[h];
    }
    #pragma unroll
    for (int o = 16; o > 0; o >>= 1) s += __shfl_xor_sync(0xffffffffu, s, o);
    if (lane == 0) g_q[b * ADIM + a] = s;
}

// ---------------------------------------------------------------------------
// Kernel 1b: r[b,h] = scale * sum_a Wk[a,h] * q[b,a]
// ---------------------------------------------------------------------------
__global__ void __launch_bounds__(160) k_r(const float* __restrict__ Wk,
                                           float scale) {
    int b = blockIdx.x;
    int h = blockIdx.y * 160 + threadIdx.x;

    __shared__ float qs[ADIM];
    if (threadIdx.x < ADIM) qs[threadIdx.x] = g_q[b * ADIM + threadIdx.x];
    __syncthreads();

    float s = 0.f;
    #pragma unroll 8
    for (int a = 0; a < ADIM; a++) s += Wk[(size_t)a * HID + h] * qs[a];
    g_r[b * HID + h] = s * scale;
}

// ---------------------------------------------------------------------------
// Kernel 2: streaming pass over gene_hiddens (819 MB). Block = one (batch,
// chunk). 8 warps each stream a contiguous row range with online softmax,
// then combine the 8 partials in shared -> ONE partial per block.
// ---------------------------------------------------------------------------
__global__ void __launch_bounds__(256) k_pass1(const float* __restrict__ gh,
                                               int N) {
    int b    = blockIdx.x / CPB;
    int c    = blockIdx.x % CPB;
    int warp = threadIdx.x >> 5;
    int lane = threadIdx.x & 31;

    // rows for this block, then this warp (contiguous per warp)
    int rpb = (N + CPB - 1) / CPB;            // 1112
    int bn0 = c * rpb;
    int bn1 = min(N, bn0 + rpb);
    int rows = bn1 - bn0;
    int rpw = (rows + 7) / 8;
    int n0  = bn0 + warp * rpw;
    int n1  = min(bn1, n0 + rpw);

    const float4* rb = reinterpret_cast<const float4*>(g_r + b * HID);
    float4 rr[5], acc[5];
    #pragma unroll
    for (int k = 0; k < 5; k++) {
        rr[k]  = rb[lane + 32 * k];
        acc[k] = make_float4(0.f, 0.f, 0.f, 0.f);
    }

    float m = -1e30f, s = 0.f;
    const float4* base = reinterpret_cast<const float4*>(gh) + (size_t)b * N * (HID / 4);

    for (int n = n0; n < n1; n++) {
        const float4* p = base + (size_t)n * (HID / 4);
        float4 hv[5];
        #pragma unroll
        for (int k = 0; k < 5; k++) hv[k] = __ldcs(p + lane + 32 * k);

        float d = 0.f;
        #pragma unroll
        for (int k = 0; k < 5; k++)
            d += hv[k].x * rr[k].x + hv[k].y * rr[k].y
               + hv[k].z * rr[k].z + hv[k].w * rr[k].w;
        #pragma unroll
        for (int o = 16; o > 0; o >>= 1) d += __shfl_xor_sync(0xffffffffu, d, o);

        if (d > m) {
            float cc = __expf(m - d);
            s *= cc;
            #pragma unroll
            for (int k = 0; k < 5; k++) {
                acc[k].x *= cc; acc[k].y *= cc; acc[k].z *= cc; acc[k].w *= cc;
            }
            m = d;
        }
        float wt = __expf(d - m);
        s += wt;
        #pragma unroll
        for (int k = 0; k < 5; k++) {
            acc[k].x += wt * hv[k].x; acc[k].y += wt * hv[k].y;
            acc[k].z += wt * hv[k].z; acc[k].w += wt * hv[k].w;
        }
    }

    // ---- intra-block combine of 8 warp partials ----
    __shared__ float sm[8], ss[8];
    __shared__ float4 sacc[8][HID / 4];       // 20 KB
    if (lane == 0) { sm[warp] = m; ss[warp] = s; }
    __syncthreads();

    float M = sm[0];
    #pragma unroll
    for (int w = 1; w < 8; w++) M = fmaxf(M, sm[w]);
    float cw = __expf(m - M);                 // per-warp rescale (uniform in warp)

    #pragma unroll
    for (int k = 0; k < 5; k++) {
        float4 v = acc[k];
        v.x *= cw; v.y *= cw; v.z *= cw; v.w *= cw;
        sacc[warp][lane + 32 * k] = v;
    }
    __syncthreads();

    // 160 float4 outputs; threads 0..159 each sum 8 warps' slice
    int t = threadIdx.x;
    if (t < HID / 4) {
        float4 a = sacc[0][t];
        #pragma unroll
        for (int w = 1; w < 8; w++) {
            float4 v = sacc[w][t];
            a.x += v.x; a.y += v.y; a.z += v.z; a.w += v.w;
        }
        reinterpret_cast<float4*>(g_pacc + (size_t)(b * CPB + c) * HID)[t] = a;
    }
    if (t == 0) {
        float st = 0.f;
        #pragma unroll
        for (int w = 0; w < 8; w++) st += ss[w] * __expf(sm[w] - M);
        g_pm[b * CPB + c] = M;
        g_ps[b * CPB + c] = st;
    }
}

// ---------------------------------------------------------------------------
// Kernel 3 (fused): combine 18 block-partials -> pooled (shared), then
// y[v] = dot(Wv[v,:], pooled). grid = (B, 5), block = 256 (8 warps x 16 rows).
// ---------------------------------------------------------------------------
__global__ void __launch_bounds__(256) k_pool_y(const float* __restrict__ Wv) {
    int b = blockIdx.x;
    int t = threadIdx.x;
    int warp = t >> 5, lane = t & 31;

    __shared__ float pooled[HID];
    __shared__ float wsm[CPB];
    __shared__ float sS;

    if (t == 0) {
        float M = -1e30f;
        #pragma unroll
        for (int i = 0; i < CPB; i++) M = fmaxf(M, g_pm[b * CPB + i]);
        float S = 0.f;
        #pragma unroll
        for (int i = 0; i < CPB; i++) {
            float w = __expf(g_pm[b * CPB + i] - M);
            wsm[i] = w;
            S += w * g_ps[b * CPB + i];
        }
        sS = S;
    }
    __syncthreads();
    float invS = 1.f / sS;

    // pooled[h] across 256 threads (h = t, t+256, t+512)
    for (int h = t; h < HID; h += 256) {
        const float* pa = g_pacc + (size_t)b * CPB * HID + h;
        float a = 0.f;
        #pragma unroll
        for (int i = 0; i < CPB; i++) a += wsm[i] * pa[(size_t)i * HID];
        pooled[h] = a * invS;
    }
    __syncthreads();

    // matvec: this block handles rows [blockIdx.y*128, +128); warp gets 16
    int vbase = blockIdx.y * 128 + warp * 16;
    #pragma unroll 2
    for (int j = 0; j < 16; j++) {
        int v = vbase + j;
        const float* wr = Wv + (size_t)v * HID;
        float acc = 0.f;
        #pragma unroll
        for (int k = 0; k < HID / 32; k++) {
            int h = lane + 32 * k;
            acc += pooled[h] * wr[h];
        }
        #pragma unroll
        for (int o = 16; o > 0; o >>= 1)
            acc += __shfl_xor_sync(0xffffffffu, acc, o);
        if (lane == 0) g_y[b * HID + v] = acc;
    }
}

// ---------------------------------------------------------------------------
// Kernel 4: LayerNorm over 640. grid=B, block=640.
// ---------------------------------------------------------------------------
__device__ __forceinline__ float block_sum_640(float v, float* sred, int t) {
    int lane = t & 31, wid = t >> 5;            // 20 warps
    #pragma unroll
    for (int o = 16; o > 0; o >>= 1) v += __shfl_xor_sync(0xffffffffu, v, o);
    if (lane == 0) sred[wid] = v;
    __syncthreads();
    if (wid == 0) {
        float x = (lane < 20) ? sred[lane] : 0.f;
        #pragma unroll
        for (int o = 16; o > 0; o >>= 1) x += __shfl_xor_sync(0xffffffffu, x, o);
        if (lane == 0) sred[0] = x;
    }
    __syncthreads();
    float r = sred[0];
    __syncthreads();
    return r;
}

__global__ void __launch_bounds__(640) k_ln(const float* __restrict__ gamma,
                                            const float* __restrict__ beta,
                                            float* __restrict__ out) {
    int b = blockIdx.x;
    int t = threadIdx.x;
    __shared__ float sred[32];

    float x = g_y[b * HID + t];
    float mean = block_sum_640(x, sred, t) * (1.f / HID);
    float dx = x - mean;
    float var = block_sum_640(dx * dx, sred, t) * (1.f / HID);
    out[b * HID + t] = dx * rsqrtf(var + 1e-5f) * gamma[t] + beta[t];
}

// ---------------------------------------------------------------------------
extern "C" void kernel_launch(void* const* d_in, const int* in_sizes, int n_in,
                              void* d_out, int out_size) {
    const float* gh    = (const float*)d_in[0];
    const float* pos   = (const float*)d_in[1];
    const float* Wq    = (const float*)d_in[2];
    const float* Wk    = (const float*)d_in[3];
    const float* Wv    = (const float*)d_in[4];
    const float* gamma = (const float*)d_in[5];
    const float* beta  = (const float*)d_in[6];
    float* out = (float*)d_out;

    int B = in_sizes[1] / HID;             // 16
    int N = in_sizes[0] / (B * HID);       // 20000
    float scale = 1.0f / sqrtf((float)ADIM);

    k_q<<<(B * ADIM) / 8, 256>>>(pos, Wq);            // 256 blocks
    k_r<<<dim3(B, HID / 160), 160>>>(Wk, scale);      // 64 blocks

    k_pass1<<<B * CPB, 256>>>(gh, N);                 // 288 blocks

    k_pool_y<<<dim3(B, 5), 256>>>(Wv);                // 80 blocks
    k_ln<<<B, HID>>>(gamma, beta, out);
}

// round 5
// speedup vs baseline: 1.2660x; 1.2660x over previous
#include <cuda_runtime.h>
#include <cmath>

#define HID  640
#define ADIM 128
#define CPB  18      // chunks (blocks) per batch in pass1 -> 16*18 = 288 blocks
#define MAXB 16

// ---- device scratch (no allocations allowed) ----
__device__ float g_q[MAXB * ADIM];                 // q[b] = Wq @ pos[b]
__device__ float g_r[MAXB * HID];                  // r[b] = scale * Wk^T q[b]
__device__ float g_pacc[MAXB * CPB * HID];         // per-block partial weighted sums
__device__ float g_pm[MAXB * CPB];                 // per-block running max
__device__ float g_ps[MAXB * CPB];                 // per-block sum of exp
__device__ float g_pooled[MAXB * HID];             // normalized pooled hidden
__device__ float g_y[MAXB * HID];                  // Wv @ pooled (pre-LN)

// ---------------------------------------------------------------------------
// Kernel 1a: q[b,a] = dot(Wq[a,:], pos[b,:])   — one warp per output
// ---------------------------------------------------------------------------
__global__ void __launch_bounds__(256) k_q(const float* __restrict__ pos,
                                           const float* __restrict__ Wq) {
    int gw   = blockIdx.x * 8 + (threadIdx.x >> 5);   // 0..2047
    int lane = threadIdx.x & 31;
    int b = gw >> 7;
    int a = gw & 127;

    const float* wr = Wq + (size_t)a * HID;
    const float* pr = pos + (size_t)b * HID;
    float s = 0.f;
    #pragma unroll
    for (int k = 0; k < HID / 32; k++) {
        int h = lane + 32 * k;
        s += wr[h] * pr[h];
    }
    #pragma unroll
    for (int o = 16; o > 0; o >>= 1) s += __shfl_xor_sync(0xffffffffu, s, o);
    if (lane == 0) g_q[b * ADIM + a] = s;
}

// ---------------------------------------------------------------------------
// Kernel 1b: r[b,h] = scale * sum_a Wk[a,h] * q[b,a]
// ---------------------------------------------------------------------------
__global__ void __launch_bounds__(160) k_r(const float* __restrict__ Wk,
                                           float scale) {
    int b = blockIdx.x;
    int h = blockIdx.y * 160 + threadIdx.x;

    __shared__ float qs[ADIM];
    if (threadIdx.x < ADIM) qs[threadIdx.x] = g_q[b * ADIM + threadIdx.x];
    __syncthreads();

    float s = 0.f;
    #pragma unroll 8
    for (int a = 0; a < ADIM; a++) s += Wk[(size_t)a * HID + h] * qs[a];
    g_r[b * HID + h] = s * scale;
}

// ---------------------------------------------------------------------------
// Kernel 2: streaming pass over gene_hiddens (819 MB). Block = one (batch,
// chunk). 8 warps each stream a contiguous row range with online softmax,
// then combine the 8 partials in shared -> ONE partial per block.
// ---------------------------------------------------------------------------
__global__ void __launch_bounds__(256) k_pass1(const float* __restrict__ gh,
                                               int N) {
    int b    = blockIdx.x / CPB;
    int c    = blockIdx.x % CPB;
    int warp = threadIdx.x >> 5;
    int lane = threadIdx.x & 31;

    int rpb = (N + CPB - 1) / CPB;
    int bn0 = c * rpb;
    int bn1 = min(N, bn0 + rpb);
    int rows = bn1 - bn0;
    int rpw = (rows + 7) / 8;
    int n0  = bn0 + warp * rpw;
    int n1  = min(bn1, n0 + rpw);

    const float4* rb = reinterpret_cast<const float4*>(g_r + b * HID);
    float4 rr[5], acc[5];
    #pragma unroll
    for (int k = 0; k < 5; k++) {
        rr[k]  = rb[lane + 32 * k];
        acc[k] = make_float4(0.f, 0.f, 0.f, 0.f);
    }

    float m = -1e30f, s = 0.f;
    const float4* base = reinterpret_cast<const float4*>(gh) + (size_t)b * N * (HID / 4);

    for (int n = n0; n < n1; n++) {
        const float4* p = base + (size_t)n * (HID / 4);
        float4 hv[5];
        #pragma unroll
        for (int k = 0; k < 5; k++) hv[k] = __ldcs(p + lane + 32 * k);

        float d = 0.f;
        #pragma unroll
        for (int k = 0; k < 5; k++)
            d += hv[k].x * rr[k].x + hv[k].y * rr[k].y
               + hv[k].z * rr[k].z + hv[k].w * rr[k].w;
        #pragma unroll
        for (int o = 16; o > 0; o >>= 1) d += __shfl_xor_sync(0xffffffffu, d, o);

        if (d > m) {
            float cc = __expf(m - d);
            s *= cc;
            #pragma unroll
            for (int k = 0; k < 5; k++) {
                acc[k].x *= cc; acc[k].y *= cc; acc[k].z *= cc; acc[k].w *= cc;
            }
            m = d;
        }
        float wt = __expf(d - m);
        s += wt;
        #pragma unroll
        for (int k = 0; k < 5; k++) {
            acc[k].x += wt * hv[k].x; acc[k].y += wt * hv[k].y;
            acc[k].z += wt * hv[k].z; acc[k].w += wt * hv[k].w;
        }
    }

    // ---- intra-block combine of 8 warp partials ----
    __shared__ float sm[8], ss[8];
    __shared__ float4 sacc[8][HID / 4];       // 20 KB
    if (lane == 0) { sm[warp] = m; ss[warp] = s; }
    __syncthreads();

    float M = sm[0];
    #pragma unroll
    for (int w = 1; w < 8; w++) M = fmaxf(M, sm[w]);
    float cw = __expf(m - M);

    #pragma unroll
    for (int k = 0; k < 5; k++) {
        float4 v = acc[k];
        v.x *= cw; v.y *= cw; v.z *= cw; v.w *= cw;
        sacc[warp][lane + 32 * k] = v;
    }
    __syncthreads();

    int t = threadIdx.x;
    if (t < HID / 4) {
        float4 a = sacc[0][t];
        #pragma unroll
        for (int w = 1; w < 8; w++) {
            float4 v = sacc[w][t];
            a.x += v.x; a.y += v.y; a.z += v.z; a.w += v.w;
        }
        reinterpret_cast<float4*>(g_pacc + (size_t)(b * CPB + c) * HID)[t] = a;
    }
    if (t == 0) {
        float st = 0.f;
        #pragma unroll
        for (int w = 0; w < 8; w++) st += ss[w] * __expf(sm[w] - M);
        g_pm[b * CPB + c] = M;
        g_ps[b * CPB + c] = st;
    }
}

// ---------------------------------------------------------------------------
// Kernel 3: pooled[b,h] = (1/S) * sum_i exp(pm_i - M) * pacc[b,i,h]
// ONE THREAD PER (b,h): grid (16,5) x 128. 18 independent unrolled loads per
// thread -> 184K loads in flight chip-wide, hides DRAM latency.
// ---------------------------------------------------------------------------
__global__ void __launch_bounds__(128) k_pooled(int dummy) {
    int b = blockIdx.x;
    int h = blockIdx.y * 128 + threadIdx.x;

    float pm[CPB], w[CPB];
    #pragma unroll
    for (int i = 0; i < CPB; i++) pm[i] = g_pm[b * CPB + i];

    float M = pm[0];
    #pragma unroll
    for (int i = 1; i < CPB; i++) M = fmaxf(M, pm[i]);

    float S = 0.f;
    #pragma unroll
    for (int i = 0; i < CPB; i++) {
        w[i] = __expf(pm[i] - M);
        S += w[i] * g_ps[b * CPB + i];
    }
    float invS = 1.f / S;

    const float* pa = g_pacc + (size_t)b * CPB * HID + h;
    float a = 0.f;
    #pragma unroll
    for (int i = 0; i < CPB; i++) a += w[i] * pa[(size_t)i * HID];
    g_pooled[b * HID + h] = a * invS;
}

// ---------------------------------------------------------------------------
// Kernel 4: y[b,v] = dot(Wv[v,:], pooled[b,:])
// ONE WARP PER (b,v) = 10240 warps, 1280 blocks. v-major ordering so 16
// consecutive warps share each Wv row (L2 dedup -> ~1.6MB DRAM total).
// ---------------------------------------------------------------------------
__global__ void __launch_bounds__(256) k_y(const float* __restrict__ Wv) {
    int gw   = blockIdx.x * 8 + (threadIdx.x >> 5);   // 0..10239
    int lane = threadIdx.x & 31;
    int v = gw >> 4;       // /16
    int b = gw & 15;

    const float* wr = Wv + (size_t)v * HID;
    const float* pr = g_pooled + (size_t)b * HID;
    float s = 0.f;
    #pragma unroll
    for (int k = 0; k < HID / 32; k++) {
        int h = lane + 32 * k;
        s += wr[h] * pr[h];
    }
    #pragma unroll
    for (int o = 16; o > 0; o >>= 1) s += __shfl_xor_sync(0xffffffffu, s, o);
    if (lane == 0) g_y[b * HID + v] = s;
}

// ---------------------------------------------------------------------------
// Kernel 5: LayerNorm over 640. grid=B, block=640.
// ---------------------------------------------------------------------------
__device__ __forceinline__ float block_sum_640(float v, float* sred, int t) {
    int lane = t & 31, wid = t >> 5;            // 20 warps
    #pragma unroll
    for (int o = 16; o > 0; o >>= 1) v += __shfl_xor_sync(0xffffffffu, v, o);
    if (lane == 0) sred[wid] = v;
    __syncthreads();
    if (wid == 0) {
        float x = (lane < 20) ? sred[lane] : 0.f;
        #pragma unroll
        for (int o = 16; o > 0; o >>= 1) x += __shfl_xor_sync(0xffffffffu, x, o);
        if (lane == 0) sred[0] = x;
    }
    __syncthreads();
    float r = sred[0];
    __syncthreads();
    return r;
}

__global__ void __launch_bounds__(640) k_ln(const float* __restrict__ gamma,
                                            const float* __restrict__ beta,
                                            float* __restrict__ out) {
    int b = blockIdx.x;
    int t = threadIdx.x;
    __shared__ float sred[32];

    float x = g_y[b * HID + t];
    float mean = block_sum_640(x, sred, t) * (1.f / HID);
    float dx = x - mean;
    float var = block_sum_640(dx * dx, sred, t) * (1.f / HID);
    out[b * HID + t] = dx * rsqrtf(var + 1e-5f) * gamma[t] + beta[t];
}

// ---------------------------------------------------------------------------
extern "C" void kernel_launch(void* const* d_in, const int* in_sizes, int n_in,
                              void* d_out, int out_size) {
    const float* gh    = (const float*)d_in[0];
    const float* pos   = (const float*)d_in[1];
    const float* Wq    = (const float*)d_in[2];
    const float* Wk    = (const float*)d_in[3];
    const float* Wv    = (const float*)d_in[4];
    const float* gamma = (const float*)d_in[5];
    const float* beta  = (const float*)d_in[6];
    float* out = (float*)d_out;

    int B = in_sizes[1] / HID;             // 16
    int N = in_sizes[0] / (B * HID);       // 20000
    float scale = 1.0f / sqrtf((float)ADIM);

    k_q<<<(B * ADIM) / 8, 256>>>(pos, Wq);            // 256 blocks
    k_r<<<dim3(B, HID / 160), 160>>>(Wk, scale);      // 64 blocks

    k_pass1<<<B * CPB, 256>>>(gh, N);                 // 288 blocks

    k_pooled<<<dim3(B, HID / 128), 128>>>(0);         // 80 blocks
    k_y<<<(B * HID) / 8, 256>>>(Wv);                  // 1280 blocks
    k_ln<<<B, HID>>>(gamma, beta, out);
}